// round 9
// baseline (speedup 1.0000x reference)
#include <cuda_runtime.h>

// QuantumLayer fused single-kernel, capped at 128 regs (measured sweet spot:
// cap 80 -> heavy spill; uncapped -> 255 regs, 8 warps/SM; cap 128 -> spill-free
// with 16 warps/SM):
//  z_w(x) = sum_{u,v} C[w][u][v]*p01[u]*p23[v], features (1, cos x, sin x).
// Every block builds C in parallel (~1.5us wall), then grid-strides with
// packed f32x2 evaluation.

#define TPB    128
#define NBLK   592                 // 4 blocks/SM * 148 SMs, all resident at t=0
#define STRIDE (NBLK * TPB)

typedef unsigned long long ull;

__device__ __forceinline__ ull pk2(float lo, float hi) {
    ull r; asm("mov.b64 %0,{%1,%2};" : "=l"(r) : "f"(lo), "f"(hi)); return r;
}
__device__ __forceinline__ void upk2(ull a, float& lo, float& hi) {
    asm("mov.b64 {%0,%1},%2;" : "=f"(lo), "=f"(hi) : "l"(a));
}
__device__ __forceinline__ ull fma2(ull a, ull b, ull c) {
    ull d; asm("fma.rn.f32x2 %0,%1,%2,%3;" : "=l"(d) : "l"(a), "l"(b), "l"(c)); return d;
}
__device__ __forceinline__ ull mul2(ull a, ull b) {
    ull d; asm("mul.rn.f32x2 %0,%1,%2;" : "=l"(d) : "l"(a), "l"(b)); return d;
}

__global__ __launch_bounds__(TPB, 4)
void qlayer_fused_kernel(const float4* __restrict__ x,
                         float4* __restrict__ out,
                         int B, const float* __restrict__ weights) {
    __shared__ float sUr[16][16], sUi[16][16];
    __shared__ float sM[256 * 4];                 // [(j*16+k)*4 + w]
    __shared__ __align__(16) ull shC[162];        // [uv][{w01, w23}]

    const int tid = threadIdx.x;

    // ---- first chunk's global load issued before builder (latency hides) ----
    int idx = blockIdx.x * TPB + tid;
    float4 xv = make_float4(0.f, 0.f, 0.f, 0.f);
    if (idx < B) xv = x[idx];

    // ================= builder: weights -> C (per block, 128 thr) =============
    {
        const int i  = tid & 15;                  // row (state index)
        const int jb = tid >> 4;                  // columns jb and jb+8
        float vr0 = (i == jb)     ? 1.0f : 0.0f, vi0 = 0.0f;
        float vr1 = (i == jb + 8) ? 1.0f : 0.0f, vi1 = 0.0f;
#pragma unroll
        for (int l = 0; l < 5; ++l) {
#pragma unroll
            for (int w = 0; w < 4; ++w) {
                const float phi   = __ldg(&weights[(l * 4 + w) * 3 + 0]);
                const float theta = __ldg(&weights[(l * 4 + w) * 3 + 1]);
                const float omega = __ldg(&weights[(l * 4 + w) * 3 + 2]);
                float sp, cp, sm, cm, st, ct;
                __sincosf(0.5f * (phi + omega), &sp, &cp);
                __sincosf(0.5f * (phi - omega), &sm, &cm);
                __sincosf(0.5f * theta, &st, &ct);
                const int m = 8 >> w;
                const float pr0 = __shfl_xor_sync(0xffffffffu, vr0, m);
                const float pi0 = __shfl_xor_sync(0xffffffffu, vi0, m);
                const float pr1 = __shfl_xor_sync(0xffffffffu, vr1, m);
                const float pi1 = __shfl_xor_sync(0xffffffffu, vi1, m);
                const bool bit = (i & m) != 0;
                const float cAr = cp * ct;
                const float cAi = bit ? sp * ct : -sp * ct;
                const float cBr = bit ? cm * st : -cm * st;
                const float cBi = -sm * st;
                float t;
                t   = cAr * vr0 - cAi * vi0 + cBr * pr0 - cBi * pi0;
                vi0 = cAr * vi0 + cAi * vr0 + cBr * pi0 + cBi * pr0;
                vr0 = t;
                t   = cAr * vr1 - cAi * vi1 + cBr * pr1 - cBi * pi1;
                vi1 = cAr * vi1 + cAi * vr1 + cBr * pi1 + cBi * pr1;
                vr1 = t;
            }
            const int r = (l % 3) + 1;
#pragma unroll
            for (int w = 0; w < 4; ++w) {
                const int mc = 8 >> w;
                const int mt = 8 >> ((w + r) & 3);
                const float pr0 = __shfl_xor_sync(0xffffffffu, vr0, mt);
                const float pi0 = __shfl_xor_sync(0xffffffffu, vi0, mt);
                const float pr1 = __shfl_xor_sync(0xffffffffu, vr1, mt);
                const float pi1 = __shfl_xor_sync(0xffffffffu, vi1, mt);
                if (i & mc) { vr0 = pr0; vi0 = pi0; vr1 = pr1; vi1 = pi1; }
            }
        }
        sUr[i][jb]     = vr0;  sUi[i][jb]     = vi0;
        sUr[i][jb + 8] = vr1;  sUi[i][jb + 8] = vi1;
    }
    __syncthreads();

    {   // M_w[j][k] = sum_i sign_w(i) Re(conj U_ij * U_ik), 2 entries/thread
#pragma unroll
        for (int p = tid; p < 256; p += TPB) {
            const int j = p >> 4, k = p & 15;
            float m0 = 0.f, m1 = 0.f, m2 = 0.f, m3 = 0.f;
#pragma unroll
            for (int ii = 0; ii < 16; ++ii) {
                const float pv = sUr[ii][j] * sUr[ii][k] + sUi[ii][j] * sUi[ii][k];
                m0 += (ii & 8) ? -pv : pv;
                m1 += (ii & 4) ? -pv : pv;
                m2 += (ii & 2) ? -pv : pv;
                m3 += (ii & 1) ? -pv : pv;
            }
            sM[p * 4 + 0] = m0; sM[p * 4 + 1] = m1;
            sM[p * 4 + 2] = m2; sM[p * 4 + 3] = m3;
        }
    }
    __syncthreads();

    if (tid < 81) {  // project M_w onto (1, cos, sin)^{x4} basis
        const int t0 = tid / 27, t1 = (tid / 9) % 3, t2 = (tid / 3) % 3, t3 = tid % 3;
        const int tt[4] = {t0, t1, t2, t3};
        float a0 = 0.f, a1 = 0.f, a2 = 0.f, a3 = 0.f;
#pragma unroll
        for (int b = 0; b < 16; ++b) {
            int j = 0, k = 0; float sgn = 1.0f;
#pragma unroll
            for (int q = 0; q < 4; ++q) {
                const int o = (b >> q) & 1;
                const int ti = tt[q];
                int jq, kq;
                if (ti == 2) { jq = o; kq = 1 - o; }
                else { jq = o; kq = o; if (ti == 1 && o) sgn = -sgn; }
                j = (j << 1) | jq;
                k = (k << 1) | kq;
            }
            const float* m = &sM[(j * 16 + k) * 4];
            a0 += sgn * m[0]; a1 += sgn * m[1];
            a2 += sgn * m[2]; a3 += sgn * m[3];
        }
        const int u = t0 * 3 + t1, v = t2 * 3 + t3;
        shC[2 * (u * 9 + v)]     = pk2(a0 * 0.0625f, a1 * 0.0625f);
        shC[2 * (u * 9 + v) + 1] = pk2(a2 * 0.0625f, a3 * 0.0625f);
    }
    __syncthreads();

    // ================= evaluation: grid-stride =================
    const ulonglong2* __restrict__ C2 = reinterpret_cast<const ulonglong2*>(shC);
    const ull ONE = pk2(1.0f, 1.0f);

    while (idx < B) {
        // features for qubits 2,3 (consumes xv.z/.w)
        float c2, s2, c3, s3;
        __sincosf(xv.z, &s2, &c2);
        __sincosf(xv.w, &s3, &c3);
        ull p23[9];
        {
            const ull c2d = pk2(c2, c2), s2d = pk2(s2, s2);
            const ull c3d = pk2(c3, c3), s3d = pk2(s3, s3);
            p23[0] = ONE; p23[1] = c3d; p23[2] = s3d;
            p23[3] = c2d; p23[4] = mul2(c2d, c3d); p23[5] = mul2(c2d, s3d);
            p23[6] = s2d; p23[7] = mul2(s2d, c3d); p23[8] = mul2(s2d, s3d);
        }
        // qubits 0,1 factors (consumes xv.x/.y -> xv dead)
        float c0, s0, c1, s1;
        __sincosf(xv.x, &s0, &c0);
        __sincosf(xv.y, &s1, &c1);
        const float f0a[3] = {1.0f, c0, s0};
        const float f1a[3] = {1.0f, c1, s1};

        // prefetch next chunk into the (now dead) xv registers
        const int nidx = idx + STRIDE;
        if (nidx < B) xv = x[nidx];

        // contraction: z = sum_u p01[u] * (sum_v C[u][v] * p23[v])
        ull zlo = 0ull, zhi = 0ull;
#pragma unroll
        for (int u = 0; u < 9; ++u) {
            ull alo = 0ull, ahi = 0ull;
#pragma unroll
            for (int v = 0; v < 9; ++v) {
                const ulonglong2 c = C2[u * 9 + v];   // LDS.128 warp-uniform
                alo = fma2(c.x, p23[v], alo);
                ahi = fma2(c.y, p23[v], ahi);
            }
            const float puf = f0a[u / 3] * f1a[u % 3];  // static idx, 1.0 folds
            const ull pu = pk2(puf, puf);
            zlo = fma2(alo, pu, zlo);
            zhi = fma2(ahi, pu, zhi);
        }

        float z0, z1, z2, z3;
        upk2(zlo, z0, z1); upk2(zhi, z2, z3);
        out[idx] = make_float4(z0, z1, z2, z3);

        idx = nidx;
    }
}

// ---------------------------------------------------------------------------
extern "C" void kernel_launch(void* const* d_in, const int* in_sizes, int n_in,
                              void* d_out, int out_size) {
    int bx = 0, bw = 1;
    if (n_in >= 2 && in_sizes[0] == 60) { bx = 1; bw = 0; }
    const float* x   = (const float*)d_in[bx];
    const float* wts = (const float*)d_in[bw];
    const int B = in_sizes[bx] / 4;

    qlayer_fused_kernel<<<NBLK, TPB>>>((const float4*)x, (float4*)d_out, B, wts);
}

// round 10
// speedup vs baseline: 1.9641x; 1.9641x over previous
#include <cuda_runtime.h>

// QuantumLayer, 2-kernel split + PDL overlap:
//  z_w(x) = sum_{u,v} C[w][u][v]*p01[u]*p23[v], features (1, cos x, sin x).
// Kernel 1 (1 block): shuffle-parallel C builder -> g_C.
// Kernel 2 (PDL secondary): prologue (x load + features) overlaps the builder,
// then cudaGridDependencySynchronize() -> load C -> packed f32x2 contraction.
// EPT=2 per thread (one C-load feeds 2 elements), single wave of 1024 blocks.

#define TPB 128
#define EPT 2

typedef unsigned long long ull;

__device__ float4 g_C[81];   // [u*9+v] -> (C_w0, C_w1, C_w2, C_w3)

__device__ __forceinline__ ull pk2(float lo, float hi) {
    ull r; asm("mov.b64 %0,{%1,%2};" : "=l"(r) : "f"(lo), "f"(hi)); return r;
}
__device__ __forceinline__ void upk2(ull a, float& lo, float& hi) {
    asm("mov.b64 {%0,%1},%2;" : "=f"(lo), "=f"(hi) : "l"(a));
}
__device__ __forceinline__ ull fma2(ull a, ull b, ull c) {
    ull d; asm("fma.rn.f32x2 %0,%1,%2,%3;" : "=l"(d) : "l"(a), "l"(b), "l"(c)); return d;
}
__device__ __forceinline__ ull mul2(ull a, ull b) {
    ull d; asm("mul.rn.f32x2 %0,%1,%2;" : "=l"(d) : "l"(a), "l"(b)); return d;
}

// ---------------------------------------------------------------------------
// Kernel 1: shuffle-parallel build of C. Thread tid = j*16 + i owns U[i][j].
// ---------------------------------------------------------------------------
__global__ void build_coeff_kernel(const float* __restrict__ weights) {
    cudaTriggerProgrammaticLaunchCompletion();   // let eval's prologue start now
    __shared__ float sUr[16][16], sUi[16][16];
    __shared__ float sM[256 * 4];                // [(j*16+k)*4 + w]
    const int tid = threadIdx.x;
    const int i = tid & 15;

    float vr = (i == (tid >> 4)) ? 1.0f : 0.0f;
    float vi = 0.0f;
#pragma unroll
    for (int l = 0; l < 5; ++l) {
#pragma unroll
        for (int w = 0; w < 4; ++w) {
            const float phi   = __ldg(&weights[(l * 4 + w) * 3 + 0]);
            const float theta = __ldg(&weights[(l * 4 + w) * 3 + 1]);
            const float omega = __ldg(&weights[(l * 4 + w) * 3 + 2]);
            float sp, cp, sm, cm, st, ct;
            __sincosf(0.5f * (phi + omega), &sp, &cp);
            __sincosf(0.5f * (phi - omega), &sm, &cm);
            __sincosf(0.5f * theta, &st, &ct);
            const int m = 8 >> w;
            const float pr = __shfl_xor_sync(0xffffffffu, vr, m);
            const float pi = __shfl_xor_sync(0xffffffffu, vi, m);
            const bool bit = (i & m) != 0;
            const float cAr = cp * ct;
            const float cAi = bit ? sp * ct : -sp * ct;
            const float cBr = bit ? cm * st : -cm * st;
            const float cBi = -sm * st;
            const float nvr = cAr * vr - cAi * vi + cBr * pr - cBi * pi;
            const float nvi = cAr * vi + cAi * vr + cBr * pi + cBi * pr;
            vr = nvr; vi = nvi;
        }
        const int r = (l % 3) + 1;
#pragma unroll
        for (int w = 0; w < 4; ++w) {
            const int mc = 8 >> w;
            const int mt = 8 >> ((w + r) & 3);
            const float pr = __shfl_xor_sync(0xffffffffu, vr, mt);
            const float pi = __shfl_xor_sync(0xffffffffu, vi, mt);
            if (i & mc) { vr = pr; vi = pi; }
        }
    }
    sUr[i][tid >> 4] = vr;
    sUi[i][tid >> 4] = vi;
    __syncthreads();

    {   // M_w[j][k] = sum_i sign_w(i) Re(conj U_ij * U_ik)
        const int j = tid >> 4, k = tid & 15;
        float m0 = 0.f, m1 = 0.f, m2 = 0.f, m3 = 0.f;
#pragma unroll
        for (int ii = 0; ii < 16; ++ii) {
            const float p = sUr[ii][j] * sUr[ii][k] + sUi[ii][j] * sUi[ii][k];
            m0 += (ii & 8) ? -p : p;
            m1 += (ii & 4) ? -p : p;
            m2 += (ii & 2) ? -p : p;
            m3 += (ii & 1) ? -p : p;
        }
        sM[tid * 4 + 0] = m0; sM[tid * 4 + 1] = m1;
        sM[tid * 4 + 2] = m2; sM[tid * 4 + 3] = m3;
    }
    __syncthreads();

    if (tid < 81) {  // project M_w onto (1, cos, sin)^{x4} basis
        const int t0 = tid / 27, t1 = (tid / 9) % 3, t2 = (tid / 3) % 3, t3 = tid % 3;
        const int tt[4] = {t0, t1, t2, t3};
        float a0 = 0.f, a1 = 0.f, a2 = 0.f, a3 = 0.f;
#pragma unroll
        for (int b = 0; b < 16; ++b) {
            int j = 0, k = 0; float sgn = 1.0f;
#pragma unroll
            for (int q = 0; q < 4; ++q) {
                const int o = (b >> q) & 1;
                const int ti = tt[q];
                int jq, kq;
                if (ti == 2) { jq = o; kq = 1 - o; }
                else { jq = o; kq = o; if (ti == 1 && o) sgn = -sgn; }
                j = (j << 1) | jq;
                k = (k << 1) | kq;
            }
            const float* m = &sM[(j * 16 + k) * 4];
            a0 += sgn * m[0]; a1 += sgn * m[1];
            a2 += sgn * m[2]; a3 += sgn * m[3];
        }
        const int u = t0 * 3 + t1, v = t2 * 3 + t3;
        g_C[u * 9 + v] = make_float4(a0 * 0.0625f, a1 * 0.0625f,
                                     a2 * 0.0625f, a3 * 0.0625f);
    }
}

// ---------------------------------------------------------------------------
// Kernel 2 (PDL secondary): features in prologue, then sync, then contract.
// ---------------------------------------------------------------------------
__global__ __launch_bounds__(TPB, 7)
void qforward_kernel(const float4* __restrict__ x, float4* __restrict__ out, int B) {
    __shared__ __align__(16) ull shC[162];       // [uv][{w01, w23}]

    const int base = blockIdx.x * (TPB * EPT) + threadIdx.x;

    // ---------- prologue: independent of C, overlaps the builder ----------
    ull p01[EPT][9], p23[EPT][9];
    bool valid[EPT];
    const ull ONE = pk2(1.0f, 1.0f);
#pragma unroll
    for (int e = 0; e < EPT; ++e) {
        const int idx = base + e * TPB;
        valid[e] = (idx < B);
        const float4 xv = valid[e] ? x[idx] : make_float4(0.f, 0.f, 0.f, 0.f);
        float c0, s0, c1, s1, c2, s2, c3, s3;
        __sincosf(xv.x, &s0, &c0);
        __sincosf(xv.y, &s1, &c1);
        __sincosf(xv.z, &s2, &c2);
        __sincosf(xv.w, &s3, &c3);
        const ull c0d = pk2(c0, c0), s0d = pk2(s0, s0);
        const ull c1d = pk2(c1, c1), s1d = pk2(s1, s1);
        const ull c2d = pk2(c2, c2), s2d = pk2(s2, s2);
        const ull c3d = pk2(c3, c3), s3d = pk2(s3, s3);
        p01[e][0] = ONE; p01[e][1] = c1d; p01[e][2] = s1d;
        p01[e][3] = c0d; p01[e][4] = mul2(c0d, c1d); p01[e][5] = mul2(c0d, s1d);
        p01[e][6] = s0d; p01[e][7] = mul2(s0d, c1d); p01[e][8] = mul2(s0d, s1d);
        p23[e][0] = ONE; p23[e][1] = c3d; p23[e][2] = s3d;
        p23[e][3] = c2d; p23[e][4] = mul2(c2d, c3d); p23[e][5] = mul2(c2d, s3d);
        p23[e][6] = s2d; p23[e][7] = mul2(s2d, c3d); p23[e][8] = mul2(s2d, s3d);
    }

    // ---------- wait for builder's g_C to be visible ----------
    cudaGridDependencySynchronize();

    if (threadIdx.x < 81) {
        const float4 c = g_C[threadIdx.x];
        shC[2 * threadIdx.x]     = pk2(c.x, c.y);
        shC[2 * threadIdx.x + 1] = pk2(c.z, c.w);
    }
    __syncthreads();

    // ---------- contraction ----------
    ull zlo[EPT], zhi[EPT];
#pragma unroll
    for (int e = 0; e < EPT; ++e) { zlo[e] = 0ull; zhi[e] = 0ull; }

    const ulonglong2* __restrict__ C2 = reinterpret_cast<const ulonglong2*>(shC);
#pragma unroll
    for (int u = 0; u < 9; ++u) {
        ull alo[EPT], ahi[EPT];
#pragma unroll
        for (int e = 0; e < EPT; ++e) { alo[e] = 0ull; ahi[e] = 0ull; }
#pragma unroll
        for (int v = 0; v < 9; ++v) {
            const ulonglong2 c = C2[u * 9 + v];   // LDS.128, warp-uniform bcast
#pragma unroll
            for (int e = 0; e < EPT; ++e) {
                alo[e] = fma2(c.x, p23[e][v], alo[e]);
                ahi[e] = fma2(c.y, p23[e][v], ahi[e]);
            }
        }
#pragma unroll
        for (int e = 0; e < EPT; ++e) {
            zlo[e] = fma2(alo[e], p01[e][u], zlo[e]);
            zhi[e] = fma2(ahi[e], p01[e][u], zhi[e]);
        }
    }

#pragma unroll
    for (int e = 0; e < EPT; ++e) {
        const int idx = base + e * TPB;
        if (valid[e]) {
            float z0, z1, z2, z3;
            upk2(zlo[e], z0, z1);
            upk2(zhi[e], z2, z3);
            out[idx] = make_float4(z0, z1, z2, z3);
        }
    }
}

// ---------------------------------------------------------------------------
extern "C" void kernel_launch(void* const* d_in, const int* in_sizes, int n_in,
                              void* d_out, int out_size) {
    int bx = 0, bw = 1;
    if (n_in >= 2 && in_sizes[0] == 60) { bx = 1; bw = 0; }
    const float* x   = (const float*)d_in[bx];
    const float* wts = (const float*)d_in[bw];
    const int B = in_sizes[bx] / 4;

    build_coeff_kernel<<<1, 256>>>(wts);

    const int grid = (B + TPB * EPT - 1) / (TPB * EPT);

    cudaLaunchConfig_t cfg = {};
    cfg.gridDim  = dim3((unsigned)grid, 1, 1);
    cfg.blockDim = dim3(TPB, 1, 1);
    cudaLaunchAttribute attrs[1];
    attrs[0].id = cudaLaunchAttributeProgrammaticStreamSerialization;
    attrs[0].val.programmaticStreamSerializationAllowed = 1;
    cfg.attrs = attrs;
    cfg.numAttrs = 1;
    cudaLaunchKernelEx(&cfg, qforward_kernel, (const float4*)x, (float4*)d_out, B);
}